// round 8
// baseline (speedup 1.0000x reference)
#include <cuda_runtime.h>
#include <cstdint>
#include <cstddef>

#define CB    8
#define CIN   64
#define COUT  64
#define TDIM  512
#define FDIM  161

constexpr int NCHK  = 8;           // CIN chunks of 8
constexpr int TT    = 256;         // t-tile (GEMM N)
constexpr int NT    = TDIM / TT;   // 2
constexpr int NSTEP = 9;           // k8 steps per chunk (K_chunk = 72 = 8i * 9(m,n))
constexpr int NTHR  = 256;         // 8 warps

// A tile per (f,chunk): fragment-ordered [step][mtile(4)][lane][4] tf32, M=64
constexpr int ATILE = NSTEP * 4 * 32 * 4;   // 4608 floats = 18432 B
// X tile: [i(8)][ts(258) stride 4][n(0..2)], row stride 1037 floats (bank spread)
constexpr int SX    = 1037;
constexpr int XFLT  = 8 * SX;               // 8296 floats = 33184 B
constexpr int XELEM = 8 * 258 * 3;          // 6192 gather elements

constexpr int SM_A0 = 0;
constexpr int SM_A1 = 18432;
constexpr int SM_X0 = 36864;
constexpr int SM_X1 = SM_X0 + XFLT * 4;
constexpr int SM_TOTAL = SM_X1 + XFLT * 4;  // 103232 B

__device__ float g_wA[(size_t)FDIM * NCHK * ATILE];   // 23.7 MB

// ---------------------------------------------------------------------------
__device__ __forceinline__ void cp_async16(uint32_t s, const void* g)
{
    asm volatile("cp.async.ca.shared.global [%0], [%1], 16;\n" :: "r"(s), "l"(g));
}
__device__ __forceinline__ void cp_async4z(uint32_t s, const void* g, bool ok)
{
    int sz = ok ? 4 : 0;
    asm volatile("cp.async.ca.shared.global [%0], [%1], 4, %2;\n" :: "r"(s), "l"(g), "r"(sz));
}
__device__ __forceinline__ uint32_t smem_u32(const void* p)
{
    uint32_t a;
    asm("{ .reg .u64 t; cvta.to.shared.u64 t, %1; cvt.u32.u64 %0, t; }" : "=r"(a) : "l"(p));
    return a;
}
__device__ __forceinline__ void mma_tf32(float& d0, float& d1, float& d2, float& d3,
                                         uint32_t a0, uint32_t a1, uint32_t a2, uint32_t a3,
                                         uint32_t b0, uint32_t b1)
{
    asm volatile("mma.sync.aligned.m16n8k8.row.col.f32.tf32.tf32.f32 "
                 "{%0,%1,%2,%3}, {%4,%5,%6,%7}, {%8,%9}, {%0,%1,%2,%3};"
                 : "+f"(d0), "+f"(d1), "+f"(d2), "+f"(d3)
                 : "r"(a0), "r"(a1), "r"(a2), "r"(a3), "r"(b0), "r"(b1));
}

// ---------------------------------------------------------------------------
// Weight transform: kernel[o][i][f][m][n] -> fragment-ordered A tiles, M=64.
// Per (f,chunk): element ((s*4+mt)*32+l)*4+r holds A[row][k]:
//   row = mt*16 + (l>>2) + 8*(r&1)          (= o)
//   k   = s*8 + (l&3) + 4*(r>>1)            -> i_loc = (l&3)+4*(r>>1), (m,n) = (s/3, s%3)
// ---------------------------------------------------------------------------
__global__ void wtrans(const float* __restrict__ w)
{
    long idx = (long)blockIdx.x * 256 + threadIdx.x;
    const long total = (long)FDIM * NCHK * ATILE;
    if (idx >= total) return;
    int e    = (int)(idx % ATILE);
    int tile = (int)(idx / ATILE);
    int ch = tile & 7;
    int f  = tile >> 3;
    int r  = e & 3;
    int l  = (e >> 2) & 31;
    int mt = (e >> 7) & 3;
    int s  = e >> 9;
    int o  = mt * 16 + (l >> 2) + 8 * (r & 1);
    int i  = ch * 8 + (l & 3) + 4 * (r >> 1);
    int m  = s / 3, n = s % 3;
    float v = w[(((size_t)(o * CIN + i) * FDIM + f) * 3 + m) * 3 + n];
    uint32_t tv; asm("cvt.rna.tf32.f32 %0, %1;" : "=r"(tv) : "f"(v));
    ((uint32_t*)g_wA)[idx] = tv;
}

// ---------------------------------------------------------------------------
// Main kernel: CTA = (f, t-tile, b) -> out[b, 0:64, t0:t0+256, f]
// 8 warps: warp_m = wid&1 (32 rows), warp_n = wid>>1 (64 cols, nt=8)
// ---------------------------------------------------------------------------
__global__ void __launch_bounds__(NTHR, 1)
conv_mma(const float* __restrict__ x,
         const float* __restrict__ bias,
         float* __restrict__ out)
{
    extern __shared__ __align__(16) char smem[];
    const uint32_t sbase = smem_u32(smem);
    const int tid    = threadIdx.x;
    const int wid    = tid >> 5;
    const int lane   = tid & 31;
    const int warp_m = wid & 1;
    const int warp_n = wid >> 1;            // 0..3, 64 cols each
    const int f      = blockIdx.x;
    const int t0     = blockIdx.y * TT;
    const int b      = blockIdx.z;
    const float* xb  = x + (size_t)b * CIN * TDIM * FDIM;

    // ---- accumulators init with bias (no masking: every CTA fully valid) ----
    float D[2][8][4];
#pragma unroll
    for (int w2 = 0; w2 < 2; w2++) {
#pragma unroll
        for (int h = 0; h < 2; h++) {
            int o = warp_m * 32 + w2 * 16 + (lane >> 2) + 8 * h;
            float bv = bias[o * FDIM + f];
#pragma unroll
            for (int nt = 0; nt < 8; nt++) {
                D[w2][nt][2 * h + 0] = bv;
                D[w2][nt][2 * h + 1] = bv;
            }
        }
    }

    // ---- chunk prefetch: A (pre-packed, 16B copies) + x halo tile ----
    auto prefetch = [&](int c, int buf) {
        const float4* asrc = (const float4*)(g_wA + (size_t)(f * NCHK + c) * ATILE);
        uint32_t ad = sbase + (buf ? SM_A1 : SM_A0);
        for (int q = tid; q < ATILE / 4; q += NTHR)       // 1152 float4
            cp_async16(ad + q * 16, asrc + q);
        const float* xc = xb + (size_t)c * 8 * TDIM * FDIM;
        uint32_t xd = sbase + (buf ? SM_X1 : SM_X0);
        for (int e = tid; e < XELEM; e += NTHR) {
            unsigned ue = (unsigned)e;
            int i   = (int)(ue / 774u);                   // 258*3
            int rem = (int)(ue - (unsigned)i * 774u);
            int ts  = (int)((unsigned)rem / 3u);
            int n   = rem - ts * 3;
            int gt  = t0 - 1 + ts;
            int gf  = f - 1 + n;
            bool ok = (gt >= 0) & (gt < TDIM) & (gf >= 0) & (gf < FDIM);
            const float* src = xc + ((size_t)i * TDIM + (ok ? gt : 0)) * FDIM + (ok ? gf : 0);
            cp_async4z(xd + (uint32_t)(i * SX + ts * 4 + n) * 4u, src, ok);
        }
        asm volatile("cp.async.commit_group;\n");
    };

    prefetch(0, 0);

    for (int c = 0; c < NCHK; c++) {
        if (c + 1 < NCHK) {
            prefetch(c + 1, (c + 1) & 1);
            asm volatile("cp.async.wait_group 1;\n");
        } else {
            asm volatile("cp.async.wait_group 0;\n");
        }
        __syncthreads();

        const int buf = c & 1;
        const uint32_t* asb = (const uint32_t*)(smem + (buf ? SM_A1 : SM_A0));
        const uint32_t* xsb = (const uint32_t*)(smem + (buf ? SM_X1 : SM_X0));

        // B elem addr (floats): i_loc*SX + (t + m_s)*4 + n_s
        const int r3 = lane & 3;
#pragma unroll
        for (int s = 0; s < NSTEP; s++) {
            const int m_s = s / 3, n_s = s % 3;
            uint32_t a[2][4];
#pragma unroll
            for (int w2 = 0; w2 < 2; w2++) {
                const uint4* ap = (const uint4*)asb +
                                  ((s * 4 + warp_m * 2 + w2) * 32 + lane);
                uint4 av = *ap;
                a[w2][0] = av.x; a[w2][1] = av.y; a[w2][2] = av.z; a[w2][3] = av.w;
            }
            const int pb0 = r3 * SX + m_s * 4 + n_s;          // i_loc = lane&3
            const int pb1 = pb0 + 4 * SX;                     // i_loc + 4
            const int tB  = warp_n * 64 + (lane >> 2);
#pragma unroll
            for (int nt = 0; nt < 8; nt++) {
                int toff = (tB + nt * 8) * 4;
                uint32_t b0 = xsb[pb0 + toff];
                uint32_t b1 = xsb[pb1 + toff];
                mma_tf32(D[0][nt][0], D[0][nt][1], D[0][nt][2], D[0][nt][3],
                         a[0][0], a[0][1], a[0][2], a[0][3], b0, b1);
                mma_tf32(D[1][nt][0], D[1][nt][1], D[1][nt][2], D[1][nt][3],
                         a[1][0], a[1][1], a[1][2], a[1][3], b0, b1);
            }
        }
        __syncthreads();
    }

    // ---- epilogue: direct stores (row -> o, col -> t, fixed f) ----
#pragma unroll
    for (int w2 = 0; w2 < 2; w2++) {
#pragma unroll
        for (int h = 0; h < 2; h++) {
            int o = warp_m * 32 + w2 * 16 + (lane >> 2) + 8 * h;
            float* op = out + ((size_t)(b * COUT + o) * TDIM + t0 + warp_n * 64) * FDIM + f;
#pragma unroll
            for (int nt = 0; nt < 8; nt++) {
                int tb = nt * 8 + (lane & 3) * 2;
                op[(size_t)(tb    ) * FDIM] = D[w2][nt][2 * h + 0];
                op[(size_t)(tb + 1) * FDIM] = D[w2][nt][2 * h + 1];
            }
        }
    }
}

// ---------------------------------------------------------------------------
extern "C" void kernel_launch(void* const* d_in, const int* in_sizes, int n_in,
                              void* d_out, int out_size)
{
    const float* x    = (const float*)d_in[0];
    const float* w    = (const float*)d_in[1];
    const float* bias = (const float*)d_in[2];
    float* out        = (float*)d_out;

    cudaFuncSetAttribute(conv_mma, cudaFuncAttributeMaxDynamicSharedMemorySize, SM_TOTAL);

    const long total = (long)FDIM * NCHK * ATILE;
    wtrans<<<(unsigned)((total + 255) / 256), 256>>>(w);

    dim3 grid(FDIM, NT, CB);
    conv_mma<<<grid, NTHR, SM_TOTAL>>>(x, bias, out);
}

// round 9
// speedup vs baseline: 1.2343x; 1.2343x over previous
#include <cuda_runtime.h>
#include <cstdint>
#include <cstddef>

#define CB    8
#define CIN   64
#define COUT  64
#define TDIM  512
#define FDIM  161

constexpr int NCHK  = 8;           // CIN chunks of 8
constexpr int TT    = 256;         // t-tile (GEMM N)
constexpr int NT    = TDIM / TT;   // 2
constexpr int NSTEP = 9;           // k8 steps per chunk (K_chunk = 72 = 8i * 9(m,n))
constexpr int NTHR  = 256;         // 8 warps

// A tile per (f,chunk): fragment-ordered [step][mtile(4)][lane][4] tf32, M=64
constexpr int ATILE = NSTEP * 4 * 32 * 4;   // 4608 floats = 18432 B
// X tile: 24 rows [i_loc*3+n], each row = 264 floats over t (t0-4 .. t0+260)
constexpr int SXR   = 264;                  // row stride: 264 % 32 == 8 (bank spread)
constexpr int XROWS = 24;
constexpr int XFLT  = XROWS * SXR;          // 6336 floats = 25344 B

constexpr int SM_A0 = 0;
constexpr int SM_A1 = 18432;
constexpr int SM_X0 = 36864;
constexpr int SM_X1 = SM_X0 + XFLT * 4;     // 62208
constexpr int SM_TOTAL = SM_X1 + XFLT * 4;  // 87552 B

__device__ float g_wA[(size_t)FDIM * NCHK * ATILE];          // 23.7 MB
__device__ float g_xT[(size_t)CB * CIN * FDIM * TDIM];       // x transposed: [b*i][f][t]
__device__ float g_oT[(size_t)CB * COUT * FDIM * TDIM];      // out staging:  [b*o][f][t]

// ---------------------------------------------------------------------------
__device__ __forceinline__ void cp_async16(uint32_t s, const void* g)
{
    asm volatile("cp.async.ca.shared.global [%0], [%1], 16;\n" :: "r"(s), "l"(g));
}
__device__ __forceinline__ void cp_async16z(uint32_t s, const void* g, bool ok)
{
    int sz = ok ? 16 : 0;
    asm volatile("cp.async.ca.shared.global [%0], [%1], 16, %2;\n" :: "r"(s), "l"(g), "r"(sz));
}
__device__ __forceinline__ uint32_t smem_u32(const void* p)
{
    uint32_t a;
    asm("{ .reg .u64 t; cvta.to.shared.u64 t, %1; cvt.u32.u64 %0, t; }" : "=r"(a) : "l"(p));
    return a;
}
__device__ __forceinline__ void mma_tf32(float& d0, float& d1, float& d2, float& d3,
                                         uint32_t a0, uint32_t a1, uint32_t a2, uint32_t a3,
                                         uint32_t b0, uint32_t b1)
{
    asm volatile("mma.sync.aligned.m16n8k8.row.col.f32.tf32.tf32.f32 "
                 "{%0,%1,%2,%3}, {%4,%5,%6,%7}, {%8,%9}, {%0,%1,%2,%3};"
                 : "+f"(d0), "+f"(d1), "+f"(d2), "+f"(d3)
                 : "r"(a0), "r"(a1), "r"(a2), "r"(a3), "r"(b0), "r"(b1));
}

// ---------------------------------------------------------------------------
// x transpose: x[b,i,t,f] -> g_xT[(b*64+i)][f][t]
// ---------------------------------------------------------------------------
__global__ void xtrans(const float* __restrict__ x)
{
    __shared__ float tile[32][33];
    const int plane = blockIdx.z;
    const int f0 = blockIdx.x * 32, tg0 = blockIdx.y * 32;
    const float* src = x + (size_t)plane * TDIM * FDIM;
#pragma unroll
    for (int r = threadIdx.y; r < 32; r += 8) {
        int f = f0 + threadIdx.x;
        tile[r][threadIdx.x] = (f < FDIM) ? src[(size_t)(tg0 + r) * FDIM + f] : 0.f;
    }
    __syncthreads();
    float* dst = g_xT + (size_t)plane * FDIM * TDIM;
#pragma unroll
    for (int r = threadIdx.y; r < 32; r += 8) {
        int f = f0 + r;
        if (f < FDIM) dst[(size_t)f * TDIM + tg0 + threadIdx.x] = tile[threadIdx.x][r];
    }
}

// ---------------------------------------------------------------------------
// out transpose: g_oT[(b*64+o)][f][t] -> out[b,o,t,f]
// ---------------------------------------------------------------------------
__global__ void otrans(float* __restrict__ out)
{
    __shared__ float tile[32][33];
    const int plane = blockIdx.z;
    const int tg0 = blockIdx.x * 32, f0 = blockIdx.y * 32;
    const float* src = g_oT + (size_t)plane * FDIM * TDIM;
#pragma unroll
    for (int r = threadIdx.y; r < 32; r += 8) {
        int f = f0 + r;
        if (f < FDIM) tile[r][threadIdx.x] = src[(size_t)f * TDIM + tg0 + threadIdx.x];
    }
    __syncthreads();
    float* dst = out + (size_t)plane * TDIM * FDIM;
#pragma unroll
    for (int r = threadIdx.y; r < 32; r += 8) {
        int f = f0 + threadIdx.x;
        if (f < FDIM) dst[(size_t)(tg0 + r) * FDIM + f] = tile[threadIdx.x][r];
    }
}

// ---------------------------------------------------------------------------
// Weight transform: kernel[o][i][f][m][n] -> fragment-ordered A tiles, M=64.
// Per (f,chunk): element ((s*4+mt)*32+l)*4+r holds A[row][k]:
//   row = mt*16 + (l>>2) + 8*(r&1)  (= o)
//   k   = s*8 + (l&3) + 4*(r>>1)    -> i_loc = (l&3)+4*(r>>1), (m,n) = (s/3, s%3)
// ---------------------------------------------------------------------------
__global__ void wtrans(const float* __restrict__ w)
{
    long idx = (long)blockIdx.x * 256 + threadIdx.x;
    const long total = (long)FDIM * NCHK * ATILE;
    if (idx >= total) return;
    int e    = (int)(idx % ATILE);
    int tile = (int)(idx / ATILE);
    int ch = tile & 7;
    int f  = tile >> 3;
    int r  = e & 3;
    int l  = (e >> 2) & 31;
    int mt = (e >> 7) & 3;
    int s  = e >> 9;
    int o  = mt * 16 + (l >> 2) + 8 * (r & 1);
    int i  = ch * 8 + (l & 3) + 4 * (r >> 1);
    int m  = s / 3, n = s % 3;
    float v = w[(((size_t)(o * CIN + i) * FDIM + f) * 3 + m) * 3 + n];
    uint32_t tv; asm("cvt.rna.tf32.f32 %0, %1;" : "=r"(tv) : "f"(v));
    ((uint32_t*)g_wA)[idx] = tv;
}

// ---------------------------------------------------------------------------
// Main kernel: CTA = (f, t-tile, b) -> oT[b*64+o][f][t0:t0+256]
// 8 warps: warp_m = wid&1 (32 rows), warp_n = wid>>1 (64 cols, nt=8)
// ---------------------------------------------------------------------------
__global__ void __launch_bounds__(NTHR, 1)
conv_mma(const float* __restrict__ bias)
{
    extern __shared__ __align__(16) char smem[];
    const uint32_t sbase = smem_u32(smem);
    const int tid    = threadIdx.x;
    const int wid    = tid >> 5;
    const int lane   = tid & 31;
    const int warp_m = wid & 1;
    const int warp_n = wid >> 1;            // 0..3, 64 cols each
    const int f      = blockIdx.x;
    const int t0     = blockIdx.y * TT;
    const int b      = blockIdx.z;

    // ---- accumulators init with bias ----
    float D[2][8][4];
#pragma unroll
    for (int w2 = 0; w2 < 2; w2++) {
#pragma unroll
        for (int h = 0; h < 2; h++) {
            int o = warp_m * 32 + w2 * 16 + (lane >> 2) + 8 * h;
            float bv = bias[o * FDIM + f];
#pragma unroll
            for (int nt = 0; nt < 8; nt++) {
                D[w2][nt][2 * h + 0] = bv;
                D[w2][nt][2 * h + 1] = bv;
            }
        }
    }

    // ---- chunk prefetch: A (pre-packed) + xT rows, all 16B cp.async ----
    auto prefetch = [&](int c, int buf) {
        const float4* asrc = (const float4*)(g_wA + (size_t)(f * NCHK + c) * ATILE);
        uint32_t ad = sbase + (buf ? SM_A1 : SM_A0);
        for (int q = tid; q < ATILE / 4; q += NTHR)       // 1152 float4
            cp_async16(ad + q * 16, asrc + q);
        uint32_t xd = sbase + (buf ? SM_X1 : SM_X0);
        const int i0 = c * 8;
        for (int e = tid; e < XROWS * 66; e += NTHR) {    // 1584 float4
            int r  = e / 66;
            int j4 = e - r * 66;
            int il = r / 3;
            int n  = r - il * 3;
            int fq = f - 1 + n;
            int ts = t0 - 4 + j4 * 4;
            bool ok = (fq >= 0) & (fq < FDIM) & (ts >= 0) & (ts < TDIM);
            const float* src = g_xT + ((size_t)(b * CIN + i0 + il) * FDIM + (ok ? fq : 0)) * TDIM
                                    + (ok ? ts : 0);
            cp_async16z(xd + (uint32_t)(r * SXR + j4 * 4) * 4u, src, ok);
        }
        asm volatile("cp.async.commit_group;\n");
    };

    prefetch(0, 0);

    for (int c = 0; c < NCHK; c++) {
        if (c + 1 < NCHK) {
            prefetch(c + 1, (c + 1) & 1);
            asm volatile("cp.async.wait_group 1;\n");
        } else {
            asm volatile("cp.async.wait_group 0;\n");
        }
        __syncthreads();

        const int buf = c & 1;
        const uint32_t* asb = (const uint32_t*)(smem + (buf ? SM_A1 : SM_A0));
        const uint32_t* xsb = (const uint32_t*)(smem + (buf ? SM_X1 : SM_X0));

        const int r3 = lane & 3;
        const int tB = warp_n * 64 + (lane >> 2);
#pragma unroll
        for (int s = 0; s < NSTEP; s++) {
            const int m_s = s / 3, n_s = s % 3;
            uint32_t a[2][4];
#pragma unroll
            for (int w2 = 0; w2 < 2; w2++) {
                const uint4* ap = (const uint4*)asb +
                                  ((s * 4 + warp_m * 2 + w2) * 32 + lane);
                uint4 av = *ap;
                a[w2][0] = av.x; a[w2][1] = av.y; a[w2][2] = av.z; a[w2][3] = av.w;
            }
            // B elem addr (floats): (i_loc*3 + n_s)*SXR + 3 + m_s + t
            const uint32_t* brow = xsb + (r3 * 3 + n_s) * SXR + 3 + m_s + tB;
#pragma unroll
            for (int nt = 0; nt < 8; nt++) {
                uint32_t b0 = brow[nt * 8];
                uint32_t b1 = brow[nt * 8 + 12 * SXR];     // i_loc + 4
                mma_tf32(D[0][nt][0], D[0][nt][1], D[0][nt][2], D[0][nt][3],
                         a[0][0], a[0][1], a[0][2], a[0][3], b0, b1);
                mma_tf32(D[1][nt][0], D[1][nt][1], D[1][nt][2], D[1][nt][3],
                         a[1][0], a[1][1], a[1][2], a[1][3], b0, b1);
            }
        }
        __syncthreads();
    }

    // ---- epilogue: coalesced float2 stores along t into g_oT ----
#pragma unroll
    for (int w2 = 0; w2 < 2; w2++) {
#pragma unroll
        for (int h = 0; h < 2; h++) {
            int o = warp_m * 32 + w2 * 16 + (lane >> 2) + 8 * h;
            float* op = g_oT + ((size_t)(b * COUT + o) * FDIM + f) * TDIM + t0 + warp_n * 64;
#pragma unroll
            for (int nt = 0; nt < 8; nt++) {
                int tb = nt * 8 + (lane & 3) * 2;
                *reinterpret_cast<float2*>(op + tb) =
                    make_float2(D[w2][nt][2 * h + 0], D[w2][nt][2 * h + 1]);
            }
        }
    }
}

// ---------------------------------------------------------------------------
extern "C" void kernel_launch(void* const* d_in, const int* in_sizes, int n_in,
                              void* d_out, int out_size)
{
    const float* x    = (const float*)d_in[0];
    const float* w    = (const float*)d_in[1];
    const float* bias = (const float*)d_in[2];
    float* out        = (float*)d_out;

    cudaFuncSetAttribute(conv_mma, cudaFuncAttributeMaxDynamicSharedMemorySize, SM_TOTAL);

    dim3 tb(32, 8);
    xtrans<<<dim3((FDIM + 31) / 32, TDIM / 32, CB * CIN), tb>>>(x);

    const long total = (long)FDIM * NCHK * ATILE;
    wtrans<<<(unsigned)((total + 255) / 256), 256>>>(w);

    dim3 grid(FDIM, NT, CB);
    conv_mma<<<grid, NTHR, SM_TOTAL>>>(bias);

    otrans<<<dim3(TDIM / 32, (FDIM + 31) / 32, CB * COUT), tb>>>(out);
}

// round 10
// speedup vs baseline: 1.8812x; 1.5241x over previous
#include <cuda_runtime.h>
#include <cuda_fp16.h>
#include <cstdint>
#include <cstddef>

#define CB    8
#define CIN   64
#define COUT  64
#define TDIM  512
#define FDIM  161

constexpr int NCHK  = 4;           // chunks of 16 channels (8 half2 pairs)
constexpr int TT    = 256;         // t-tile (GEMM N)
constexpr int NT    = TDIM / TT;   // 2
constexpr int NSTEP = 9;           // k16 steps per chunk (K_chunk = 144 = 16i * 9(m,n))
constexpr int NTHR  = 256;         // 8 warps

// A tile per (f,chunk): fragment-ordered half2 words [step][mtile(4)][lane][4]
constexpr int ATILE_W = NSTEP * 4 * 32 * 4;   // 4608 words = 18432 B
// X tile: 24 rows [ip_loc*3+n], each row = 264 half2 words over t (t0-4 .. t0+259)
constexpr int SXR   = 264;                    // word stride; 264 % 32 == 8 (bank spread)
constexpr int XROWS = 24;
constexpr int XWRD  = XROWS * SXR;            // 6336 words = 25344 B

constexpr int SM_A0 = 0;
constexpr int SM_A1 = 18432;
constexpr int SM_X0 = 36864;
constexpr int SM_X1 = SM_X0 + XWRD * 4;       // 62208
constexpr int SM_TOTAL = SM_X1 + XWRD * 4;    // 87552 B

__device__ uint32_t g_wA[(size_t)FDIM * NCHK * ATILE_W];      // 11.9 MB (half2 words)
__device__ uint32_t g_xh[(size_t)CB * 32 * FDIM * TDIM];      // x: [b*ip][f][t] half2 pairs
__device__ float    g_oT[(size_t)CB * COUT * FDIM * TDIM];    // out staging: [b*o][f][t]

// ---------------------------------------------------------------------------
__device__ __forceinline__ void cp_async16(uint32_t s, const void* g)
{
    asm volatile("cp.async.ca.shared.global [%0], [%1], 16;\n" :: "r"(s), "l"(g));
}
__device__ __forceinline__ void cp_async16z(uint32_t s, const void* g, bool ok)
{
    int sz = ok ? 16 : 0;
    asm volatile("cp.async.ca.shared.global [%0], [%1], 16, %2;\n" :: "r"(s), "l"(g), "r"(sz));
}
__device__ __forceinline__ uint32_t smem_u32(const void* p)
{
    uint32_t a;
    asm("{ .reg .u64 t; cvta.to.shared.u64 t, %1; cvt.u32.u64 %0, t; }" : "=r"(a) : "l"(p));
    return a;
}
__device__ __forceinline__ void mma_f16(float& d0, float& d1, float& d2, float& d3,
                                        uint32_t a0, uint32_t a1, uint32_t a2, uint32_t a3,
                                        uint32_t b0, uint32_t b1)
{
    asm volatile("mma.sync.aligned.m16n8k16.row.col.f32.f16.f16.f32 "
                 "{%0,%1,%2,%3}, {%4,%5,%6,%7}, {%8,%9}, {%0,%1,%2,%3};"
                 : "+f"(d0), "+f"(d1), "+f"(d2), "+f"(d3)
                 : "r"(a0), "r"(a1), "r"(a2), "r"(a3), "r"(b0), "r"(b1));
}
__device__ __forceinline__ uint32_t pack_h2(float lo, float hi)
{
    __half2 h = __floats2half2_rn(lo, hi);
    return *reinterpret_cast<uint32_t*>(&h);
}

// ---------------------------------------------------------------------------
// x transform: x[b, i, t, f] -> g_xh[(b*32+ip)][f][t] = half2{x[2ip], x[2ip+1]}
// ---------------------------------------------------------------------------
__global__ void xtrans(const float* __restrict__ x)
{
    __shared__ uint32_t tile[32][33];
    const int plane = blockIdx.z;            // b*32 + ip
    const int b  = plane >> 5;
    const int ip = plane & 31;
    const int f0 = blockIdx.x * 32, tg0 = blockIdx.y * 32;
    const float* s0 = x + (size_t)(b * CIN + 2 * ip    ) * TDIM * FDIM;
    const float* s1 = x + (size_t)(b * CIN + 2 * ip + 1) * TDIM * FDIM;
#pragma unroll
    for (int r = threadIdx.y; r < 32; r += 8) {
        int f = f0 + threadIdx.x;
        float v0 = 0.f, v1 = 0.f;
        if (f < FDIM) {
            size_t off = (size_t)(tg0 + r) * FDIM + f;
            v0 = s0[off]; v1 = s1[off];
        }
        tile[r][threadIdx.x] = pack_h2(v0, v1);
    }
    __syncthreads();
    uint32_t* dst = g_xh + (size_t)plane * FDIM * TDIM;
#pragma unroll
    for (int r = threadIdx.y; r < 32; r += 8) {
        int f = f0 + r;
        if (f < FDIM) dst[(size_t)f * TDIM + tg0 + threadIdx.x] = tile[threadIdx.x][r];
    }
}

// ---------------------------------------------------------------------------
// out transpose: g_oT[(b*64+o)][f][t] -> out[b,o,t,f]
// ---------------------------------------------------------------------------
__global__ void otrans(float* __restrict__ out)
{
    __shared__ float tile[32][33];
    const int plane = blockIdx.z;
    const int tg0 = blockIdx.x * 32, f0 = blockIdx.y * 32;
    const float* src = g_oT + (size_t)plane * FDIM * TDIM;
#pragma unroll
    for (int r = threadIdx.y; r < 32; r += 8) {
        int f = f0 + r;
        if (f < FDIM) tile[r][threadIdx.x] = src[(size_t)f * TDIM + tg0 + threadIdx.x];
    }
    __syncthreads();
    float* dst = out + (size_t)plane * TDIM * FDIM;
#pragma unroll
    for (int r = threadIdx.y; r < 32; r += 8) {
        int f = f0 + threadIdx.x;
        if (f < FDIM) dst[(size_t)(tg0 + r) * FDIM + f] = tile[threadIdx.x][r];
    }
}

// ---------------------------------------------------------------------------
// Weight transform -> m16n8k16 fragment-ordered half2 A tiles, M=64, K=144/chunk.
// Word ((s*4+mt)*32+l)*4+r holds half2{A[o][k], A[o][k+1]}:
//   o = mt*16 + (l>>2) + 8*(r&1)
//   ip = (l&3) + 4*(r>>1);  i_even = ch*16 + 2*ip;  (m,n) = (s/3, s%3)
// ---------------------------------------------------------------------------
__global__ void wtrans(const float* __restrict__ w)
{
    long idx = (long)blockIdx.x * 256 + threadIdx.x;
    const long total = (long)FDIM * NCHK * ATILE_W;
    if (idx >= total) return;
    int e    = (int)(idx % ATILE_W);
    int tile = (int)(idx / ATILE_W);
    int ch = tile & 3;
    int f  = tile >> 2;
    int r  = e & 3;
    int l  = (e >> 2) & 31;
    int mt = (e >> 7) & 3;
    int s  = e >> 9;
    int o  = mt * 16 + (l >> 2) + 8 * (r & 1);
    int ip = (l & 3) + 4 * (r >> 1);
    int i0 = ch * 16 + 2 * ip;
    int m  = s / 3, n = s % 3;
    float v0 = w[(((size_t)(o * CIN + i0    ) * FDIM + f) * 3 + m) * 3 + n];
    float v1 = w[(((size_t)(o * CIN + i0 + 1) * FDIM + f) * 3 + m) * 3 + n];
    g_wA[idx] = pack_h2(v0, v1);
}

// ---------------------------------------------------------------------------
// Main kernel: CTA = (f, t-tile, b) -> g_oT[b*64+o][f][t0:t0+256]
// 8 warps: warp_m = wid&1 (32 rows), warp_n = wid>>1 (64 cols, nt=8)
// ---------------------------------------------------------------------------
__global__ void __launch_bounds__(NTHR, 1)
conv_mma(const float* __restrict__ bias)
{
    extern __shared__ __align__(16) char smem[];
    const uint32_t sbase = smem_u32(smem);
    const int tid    = threadIdx.x;
    const int wid    = tid >> 5;
    const int lane   = tid & 31;
    const int warp_m = wid & 1;
    const int warp_n = wid >> 1;            // 0..3, 64 cols each
    const int f      = blockIdx.x;
    const int t0     = blockIdx.y * TT;
    const int b      = blockIdx.z;

    // ---- accumulators init with bias ----
    float D[2][8][4];
#pragma unroll
    for (int w2 = 0; w2 < 2; w2++) {
#pragma unroll
        for (int h = 0; h < 2; h++) {
            int o = warp_m * 32 + w2 * 16 + (lane >> 2) + 8 * h;
            float bv = bias[o * FDIM + f];
#pragma unroll
            for (int nt = 0; nt < 8; nt++) {
                D[w2][nt][2 * h + 0] = bv;
                D[w2][nt][2 * h + 1] = bv;
            }
        }
    }

    // ---- chunk prefetch: A (pre-packed) + xh rows, all 16B cp.async ----
    auto prefetch = [&](int c, int buf) {
        const float4* asrc = (const float4*)(g_wA + (size_t)(f * NCHK + c) * ATILE_W);
        uint32_t ad = sbase + (buf ? SM_A1 : SM_A0);
        for (int q = tid; q < ATILE_W / 4; q += NTHR)      // 1152 float4
            cp_async16(ad + q * 16, asrc + q);
        uint32_t xd = sbase + (buf ? SM_X1 : SM_X0);
        for (int e = tid; e < XROWS * 66; e += NTHR) {     // 1584 float4
            int r  = e / 66;
            int j4 = e - r * 66;
            int il = r / 3;
            int n  = r - il * 3;
            int fq = f - 1 + n;
            int ts = t0 - 4 + j4 * 4;
            bool ok = (fq >= 0) & (fq < FDIM) & (ts >= 0) & (ts < TDIM);
            const uint32_t* src = g_xh + ((size_t)(b * 32 + c * 8 + il) * FDIM + (ok ? fq : 0)) * TDIM
                                       + (ok ? ts : 0);
            cp_async16z(xd + (uint32_t)(r * SXR + j4 * 4) * 4u, src, ok);
        }
        asm volatile("cp.async.commit_group;\n");
    };

    prefetch(0, 0);

    for (int c = 0; c < NCHK; c++) {
        if (c + 1 < NCHK) {
            prefetch(c + 1, (c + 1) & 1);
            asm volatile("cp.async.wait_group 1;\n");
        } else {
            asm volatile("cp.async.wait_group 0;\n");
        }
        __syncthreads();

        const int buf = c & 1;
        const uint32_t* asb = (const uint32_t*)(smem + (buf ? SM_A1 : SM_A0));
        const uint32_t* xsb = (const uint32_t*)(smem + (buf ? SM_X1 : SM_X0));

        const int r3 = lane & 3;
        const int tB = warp_n * 64 + (lane >> 2);
#pragma unroll
        for (int s = 0; s < NSTEP; s++) {
            const int m_s = s / 3, n_s = s % 3;
            uint32_t a[2][4];
#pragma unroll
            for (int w2 = 0; w2 < 2; w2++) {
                const uint4* ap = (const uint4*)asb +
                                  ((s * 4 + warp_m * 2 + w2) * 32 + lane);
                uint4 av = *ap;
                a[w2][0] = av.x; a[w2][1] = av.y; a[w2][2] = av.z; a[w2][3] = av.w;
            }
            // B word addr: (ip_loc*3 + n_s)*SXR + 3 + m_s + t ; b1 at ip_loc+4
            const uint32_t* brow = xsb + (r3 * 3 + n_s) * SXR + 3 + m_s + tB;
#pragma unroll
            for (int nt = 0; nt < 8; nt++) {
                uint32_t b0 = brow[nt * 8];
                uint32_t b1 = brow[nt * 8 + 12 * SXR];
                mma_f16(D[0][nt][0], D[0][nt][1], D[0][nt][2], D[0][nt][3],
                        a[0][0], a[0][1], a[0][2], a[0][3], b0, b1);
                mma_f16(D[1][nt][0], D[1][nt][1], D[1][nt][2], D[1][nt][3],
                        a[1][0], a[1][1], a[1][2], a[1][3], b0, b1);
            }
        }
        __syncthreads();
    }

    // ---- epilogue: coalesced float2 stores along t into g_oT ----
#pragma unroll
    for (int w2 = 0; w2 < 2; w2++) {
#pragma unroll
        for (int h = 0; h < 2; h++) {
            int o = warp_m * 32 + w2 * 16 + (lane >> 2) + 8 * h;
            float* op = g_oT + ((size_t)(b * COUT + o) * FDIM + f) * TDIM + t0 + warp_n * 64;
#pragma unroll
            for (int nt = 0; nt < 8; nt++) {
                int tb = nt * 8 + (lane & 3) * 2;
                *reinterpret_cast<float2*>(op + tb) =
                    make_float2(D[w2][nt][2 * h + 0], D[w2][nt][2 * h + 1]);
            }
        }
    }
}

// ---------------------------------------------------------------------------
extern "C" void kernel_launch(void* const* d_in, const int* in_sizes, int n_in,
                              void* d_out, int out_size)
{
    const float* x    = (const float*)d_in[0];
    const float* w    = (const float*)d_in[1];
    const float* bias = (const float*)d_in[2];
    float* out        = (float*)d_out;

    cudaFuncSetAttribute(conv_mma, cudaFuncAttributeMaxDynamicSharedMemorySize, SM_TOTAL);

    dim3 tb(32, 8);
    xtrans<<<dim3((FDIM + 31) / 32, TDIM / 32, CB * 32), tb>>>(x);

    const long total = (long)FDIM * NCHK * ATILE_W;
    wtrans<<<(unsigned)((total + 255) / 256), 256>>>(w);

    dim3 grid(FDIM, NT, CB);
    conv_mma<<<grid, NTHR, SM_TOTAL>>>(bias);

    otrans<<<dim3(TDIM / 32, (FDIM + 31) / 32, CB * COUT), tb>>>(out);
}

// round 11
// speedup vs baseline: 2.1476x; 1.1416x over previous
#include <cuda_runtime.h>
#include <cuda_fp16.h>
#include <cstdint>
#include <cstddef>

#define CB    8
#define CIN   64
#define COUT  64
#define TDIM  512
#define FDIM  161

constexpr int NCHK  = 4;           // chunks of 16 channels (8 half2 pairs)
constexpr int TT    = 256;         // t-tile (GEMM N)
constexpr int NT    = TDIM / TT;   // 2
constexpr int NSTEP = 9;           // k16 steps per chunk (K_chunk = 144 = 16i * 9(m,n))
constexpr int NTHR  = 256;         // 8 warps

// A tile per (f,chunk): fragment-ordered half2 words [step][mtile(4)][lane][4]
constexpr int ATILE_W = NSTEP * 4 * 32 * 4;   // 4608 words = 18432 B
// X tile: 24 rows [ip_loc*3+n], each row = 264 half2 words over t (t0-4 .. t0+259)
constexpr int SXR   = 264;                    // word stride; 264 % 32 == 8 (bank spread)
constexpr int XROWS = 24;
constexpr int XWRD  = XROWS * SXR;            // 6336 words = 25344 B

constexpr int SM_A0 = 0;
constexpr int SM_A1 = 18432;
constexpr int SM_X0 = 36864;
constexpr int SM_X1 = SM_X0 + XWRD * 4;       // 62208
constexpr int SM_TOTAL = SM_X1 + XWRD * 4;    // 87552 B

__device__ uint32_t g_wA[(size_t)FDIM * NCHK * ATILE_W];      // 11.9 MB (half2 words)
__device__ uint32_t g_xh[(size_t)CB * 32 * FDIM * TDIM];      // x: [b*ip][f][t] half2 pairs
__device__ uint32_t g_oh[(size_t)CB * COUT * FDIM * (TDIM/2)]; // out staging: [b*o][f][t/2] half2

// ---------------------------------------------------------------------------
__device__ __forceinline__ void cp_async16(uint32_t s, const void* g)
{
    asm volatile("cp.async.ca.shared.global [%0], [%1], 16;\n" :: "r"(s), "l"(g));
}
__device__ __forceinline__ void cp_async16z(uint32_t s, const void* g, bool ok)
{
    int sz = ok ? 16 : 0;
    asm volatile("cp.async.ca.shared.global [%0], [%1], 16, %2;\n" :: "r"(s), "l"(g), "r"(sz));
}
__device__ __forceinline__ uint32_t smem_u32(const void* p)
{
    uint32_t a;
    asm("{ .reg .u64 t; cvta.to.shared.u64 t, %1; cvt.u32.u64 %0, t; }" : "=r"(a) : "l"(p));
    return a;
}
__device__ __forceinline__ void mma_f16(float& d0, float& d1, float& d2, float& d3,
                                        uint32_t a0, uint32_t a1, uint32_t a2, uint32_t a3,
                                        uint32_t b0, uint32_t b1)
{
    asm volatile("mma.sync.aligned.m16n8k16.row.col.f32.f16.f16.f32 "
                 "{%0,%1,%2,%3}, {%4,%5,%6,%7}, {%8,%9}, {%0,%1,%2,%3};"
                 : "+f"(d0), "+f"(d1), "+f"(d2), "+f"(d3)
                 : "r"(a0), "r"(a1), "r"(a2), "r"(a3), "r"(b0), "r"(b1));
}
__device__ __forceinline__ uint32_t pack_h2(float lo, float hi)
{
    __half2 h = __floats2half2_rn(lo, hi);
    return *reinterpret_cast<uint32_t*>(&h);
}

// ---------------------------------------------------------------------------
// x transform: x[b, i, t, f] -> g_xh[(b*32+ip)][f][t] = half2{x[2ip], x[2ip+1]}
// ---------------------------------------------------------------------------
__global__ void xtrans(const float* __restrict__ x)
{
    __shared__ uint32_t tile[32][33];
    const int plane = blockIdx.z;            // b*32 + ip
    const int b  = plane >> 5;
    const int ip = plane & 31;
    const int f0 = blockIdx.x * 32, tg0 = blockIdx.y * 32;
    const float* s0 = x + (size_t)(b * CIN + 2 * ip    ) * TDIM * FDIM;
    const float* s1 = x + (size_t)(b * CIN + 2 * ip + 1) * TDIM * FDIM;
#pragma unroll
    for (int r = threadIdx.y; r < 32; r += 8) {
        int f = f0 + threadIdx.x;
        float v0 = 0.f, v1 = 0.f;
        if (f < FDIM) {
            size_t off = (size_t)(tg0 + r) * FDIM + f;
            v0 = s0[off]; v1 = s1[off];
        }
        tile[r][threadIdx.x] = pack_h2(v0, v1);
    }
    __syncthreads();
    uint32_t* dst = g_xh + (size_t)plane * FDIM * TDIM;
#pragma unroll
    for (int r = threadIdx.y; r < 32; r += 8) {
        int f = f0 + r;
        if (f < FDIM) dst[(size_t)f * TDIM + tg0 + threadIdx.x] = tile[threadIdx.x][r];
    }
}

// ---------------------------------------------------------------------------
// out transpose: g_oh[(b*64+o)][f][t/2] (half2) -> out[b,o,t,f] (f32)
// block: 32f x 128t tile; vector uint2 reads along t, coalesced f-row writes
// ---------------------------------------------------------------------------
__global__ void __launch_bounds__(256)
otrans(float* __restrict__ out)
{
    __shared__ float tile[32][129];
    const int plane = blockIdx.z;            // b*COUT + o
    const int tg0 = blockIdx.x * 128;
    const int f0  = blockIdx.y * 32;
    const int tx  = threadIdx.x & 31;
    const int ty  = threadIdx.x >> 5;        // 0..7
    const uint32_t* src = g_oh + (size_t)plane * FDIM * (TDIM / 2);

#pragma unroll
    for (int k = 0; k < 4; k++) {
        int fl = ty + 8 * k;
        int f  = f0 + fl;
        if (f < FDIM) {
            // uint2 = 2 half2 words = 4 t values
            uint2 v = *reinterpret_cast<const uint2*>(src + (size_t)f * (TDIM / 2)
                                                      + (tg0 >> 1) + tx * 2);
            __half2 h0 = *reinterpret_cast<__half2*>(&v.x);
            __half2 h1 = *reinterpret_cast<__half2*>(&v.y);
            tile[fl][tx * 4 + 0] = __low2float(h0);
            tile[fl][tx * 4 + 1] = __high2float(h0);
            tile[fl][tx * 4 + 2] = __low2float(h1);
            tile[fl][tx * 4 + 3] = __high2float(h1);
        }
    }
    __syncthreads();

    const int f = f0 + tx;
    if (f < FDIM) {
        float* dst = out + (size_t)plane * TDIM * FDIM + (size_t)tg0 * FDIM + f;
#pragma unroll
        for (int k = 0; k < 16; k++) {
            int tl = ty * 16 + k;
            dst[(size_t)tl * FDIM] = tile[tx][tl];
        }
    }
}

// ---------------------------------------------------------------------------
// Weight transform -> m16n8k16 fragment-ordered half2 A tiles, M=64, K=144/chunk.
// ---------------------------------------------------------------------------
__global__ void wtrans(const float* __restrict__ w)
{
    long idx = (long)blockIdx.x * 256 + threadIdx.x;
    const long total = (long)FDIM * NCHK * ATILE_W;
    if (idx >= total) return;
    int e    = (int)(idx % ATILE_W);
    int tile = (int)(idx / ATILE_W);
    int ch = tile & 3;
    int f  = tile >> 2;
    int r  = e & 3;
    int l  = (e >> 2) & 31;
    int mt = (e >> 7) & 3;
    int s  = e >> 9;
    int o  = mt * 16 + (l >> 2) + 8 * (r & 1);
    int ip = (l & 3) + 4 * (r >> 1);
    int i0 = ch * 16 + 2 * ip;
    int m  = s / 3, n = s % 3;
    float v0 = w[(((size_t)(o * CIN + i0    ) * FDIM + f) * 3 + m) * 3 + n];
    float v1 = w[(((size_t)(o * CIN + i0 + 1) * FDIM + f) * 3 + m) * 3 + n];
    g_wA[idx] = pack_h2(v0, v1);
}

// ---------------------------------------------------------------------------
// Main kernel: CTA = (f, t-tile, b) -> g_oh[b*64+o][f][t0/2 : (t0+256)/2]
// 8 warps: warp_m = wid&1 (32 rows), warp_n = wid>>1 (64 cols, nt=8)
// ---------------------------------------------------------------------------
__global__ void __launch_bounds__(NTHR, 1)
conv_mma(const float* __restrict__ bias)
{
    extern __shared__ __align__(16) char smem[];
    const uint32_t sbase = smem_u32(smem);
    const int tid    = threadIdx.x;
    const int wid    = tid >> 5;
    const int lane   = tid & 31;
    const int warp_m = wid & 1;
    const int warp_n = wid >> 1;            // 0..3, 64 cols each
    const int f      = blockIdx.x;
    const int t0     = blockIdx.y * TT;
    const int b      = blockIdx.z;

    // ---- accumulators init with bias ----
    float D[2][8][4];
#pragma unroll
    for (int w2 = 0; w2 < 2; w2++) {
#pragma unroll
        for (int h = 0; h < 2; h++) {
            int o = warp_m * 32 + w2 * 16 + (lane >> 2) + 8 * h;
            float bv = bias[o * FDIM + f];
#pragma unroll
            for (int nt = 0; nt < 8; nt++) {
                D[w2][nt][2 * h + 0] = bv;
                D[w2][nt][2 * h + 1] = bv;
            }
        }
    }

    // ---- chunk prefetch: A (pre-packed) + xh rows, all 16B cp.async ----
    auto prefetch = [&](int c, int buf) {
        const float4* asrc = (const float4*)(g_wA + (size_t)(f * NCHK + c) * ATILE_W);
        uint32_t ad = sbase + (buf ? SM_A1 : SM_A0);
        for (int q = tid; q < ATILE_W / 4; q += NTHR)      // 1152 float4
            cp_async16(ad + q * 16, asrc + q);
        uint32_t xd = sbase + (buf ? SM_X1 : SM_X0);
        for (int e = tid; e < XROWS * 66; e += NTHR) {     // 1584 float4
            int r  = e / 66;
            int j4 = e - r * 66;
            int il = r / 3;
            int n  = r - il * 3;
            int fq = f - 1 + n;
            int ts = t0 - 4 + j4 * 4;
            bool ok = (fq >= 0) & (fq < FDIM) & (ts >= 0) & (ts < TDIM);
            const uint32_t* src = g_xh + ((size_t)(b * 32 + c * 8 + il) * FDIM + (ok ? fq : 0)) * TDIM
                                       + (ok ? ts : 0);
            cp_async16z(xd + (uint32_t)(r * SXR + j4 * 4) * 4u, src, ok);
        }
        asm volatile("cp.async.commit_group;\n");
    };

    prefetch(0, 0);

    for (int c = 0; c < NCHK; c++) {
        if (c + 1 < NCHK) {
            prefetch(c + 1, (c + 1) & 1);
            asm volatile("cp.async.wait_group 1;\n");
        } else {
            asm volatile("cp.async.wait_group 0;\n");
        }
        __syncthreads();

        const int buf = c & 1;
        const uint32_t* asb = (const uint32_t*)(smem + (buf ? SM_A1 : SM_A0));
        const uint32_t* xsb = (const uint32_t*)(smem + (buf ? SM_X1 : SM_X0));

        const int r3 = lane & 3;
        const int tB = warp_n * 64 + (lane >> 2);
#pragma unroll
        for (int s = 0; s < NSTEP; s++) {
            const int m_s = s / 3, n_s = s % 3;
            uint32_t a[2][4];
#pragma unroll
            for (int w2 = 0; w2 < 2; w2++) {
                const uint4* ap = (const uint4*)asb +
                                  ((s * 4 + warp_m * 2 + w2) * 32 + lane);
                uint4 av = *ap;
                a[w2][0] = av.x; a[w2][1] = av.y; a[w2][2] = av.z; a[w2][3] = av.w;
            }
            // B word addr: (ip_loc*3 + n_s)*SXR + 3 + m_s + t ; b1 at ip_loc+4
            const uint32_t* brow = xsb + (r3 * 3 + n_s) * SXR + 3 + m_s + tB;
#pragma unroll
            for (int nt = 0; nt < 8; nt++) {
                uint32_t b0 = brow[nt * 8];
                uint32_t b1 = brow[nt * 8 + 12 * SXR];
                mma_f16(D[0][nt][0], D[0][nt][1], D[0][nt][2], D[0][nt][3],
                        a[0][0], a[0][1], a[0][2], a[0][3], b0, b1);
                mma_f16(D[1][nt][0], D[1][nt][1], D[1][nt][2], D[1][nt][3],
                        a[1][0], a[1][1], a[1][2], a[1][3], b0, b1);
            }
        }
        __syncthreads();
    }

    // ---- epilogue: half2-packed coalesced stores along t into g_oh ----
#pragma unroll
    for (int w2 = 0; w2 < 2; w2++) {
#pragma unroll
        for (int h = 0; h < 2; h++) {
            int o = warp_m * 32 + w2 * 16 + (lane >> 2) + 8 * h;
            uint32_t* op = g_oh + ((size_t)(b * COUT + o) * FDIM + f) * (TDIM / 2)
                         + ((t0 + warp_n * 64) >> 1);
#pragma unroll
            for (int nt = 0; nt < 8; nt++) {
                int tw = nt * 4 + (lane & 3);   // word index (pair of t)
                op[tw] = pack_h2(D[w2][nt][2 * h + 0], D[w2][nt][2 * h + 1]);
            }
        }
    }
}

// ---------------------------------------------------------------------------
extern "C" void kernel_launch(void* const* d_in, const int* in_sizes, int n_in,
                              void* d_out, int out_size)
{
    const float* x    = (const float*)d_in[0];
    const float* w    = (const float*)d_in[1];
    const float* bias = (const float*)d_in[2];
    float* out        = (float*)d_out;

    cudaFuncSetAttribute(conv_mma, cudaFuncAttributeMaxDynamicSharedMemorySize, SM_TOTAL);

    dim3 tb(32, 8);
    xtrans<<<dim3((FDIM + 31) / 32, TDIM / 32, CB * 32), tb>>>(x);

    const long total = (long)FDIM * NCHK * ATILE_W;
    wtrans<<<(unsigned)((total + 255) / 256), 256>>>(w);

    dim3 grid(FDIM, NT, CB);
    conv_mma<<<grid, NTHR, SM_TOTAL>>>(bias);

    otrans<<<dim3(TDIM / 128, (FDIM + 31) / 32, CB * COUT), 256>>>(out);
}

// round 13
// speedup vs baseline: 2.3482x; 1.0934x over previous
#include <cuda_runtime.h>
#include <cuda_fp16.h>
#include <cstdint>
#include <cstddef>

#define CB    8
#define CIN   64
#define COUT  64
#define TDIM  512
#define FDIM  161

constexpr int NCHK  = 4;           // chunks of 16 channels (8 half2 pairs)
constexpr int TT    = 256;         // t-tile (GEMM N)
constexpr int NT    = TDIM / TT;   // 2
constexpr int NSTEP = 9;           // k16 steps per chunk (K_chunk = 144 = 16i * 9(m,n))
constexpr int NTHR  = 256;         // 8 warps

// A tile per (f,chunk): fragment-ordered half2 words [step][mtile(4)][lane][4]
constexpr int ATILE_W = NSTEP * 4 * 32 * 4;   // 4608 words = 18432 B
// X tile: 24 rows [ip_loc*3+n], each row = 264 half2 words over t (t0-4 .. t0+259)
constexpr int SXR   = 264;                    // word stride; 264 % 32 == 8 (bank spread)
constexpr int XROWS = 24;
constexpr int XWRD  = XROWS * SXR;            // 6336 words = 25344 B

constexpr int SM_A0 = 0;
constexpr int SM_A1 = 18432;
constexpr int SM_X0 = 36864;
constexpr int SM_X1 = SM_X0 + XWRD * 4;       // 62208
constexpr int SM_TOTAL = SM_X1 + XWRD * 4;    // 87552 B (x2 CTAs = 175KB <= 227KB)

__device__ uint32_t g_wA[(size_t)FDIM * NCHK * ATILE_W];      // 11.9 MB (half2 words)
__device__ uint32_t g_xh[(size_t)CB * 32 * FDIM * TDIM];      // x: [b*ip][f][t] half2 pairs
__device__ uint32_t g_oh[(size_t)CB * COUT * FDIM * (TDIM/2)]; // out staging: [b*o][f][t/2] half2

// ---------------------------------------------------------------------------
__device__ __forceinline__ void cp_async16(uint32_t s, const void* g)
{
    asm volatile("cp.async.ca.shared.global [%0], [%1], 16;\n" :: "r"(s), "l"(g));
}
__device__ __forceinline__ void cp_async16z(uint32_t s, const void* g, bool ok)
{
    int sz = ok ? 16 : 0;
    asm volatile("cp.async.ca.shared.global [%0], [%1], 16, %2;\n" :: "r"(s), "l"(g), "r"(sz));
}
__device__ __forceinline__ uint32_t smem_u32(const void* p)
{
    uint32_t a;
    asm("{ .reg .u64 t; cvta.to.shared.u64 t, %1; cvt.u32.u64 %0, t; }" : "=r"(a) : "l"(p));
    return a;
}
__device__ __forceinline__ void mma_f16(float& d0, float& d1, float& d2, float& d3,
                                        uint32_t a0, uint32_t a1, uint32_t a2, uint32_t a3,
                                        uint32_t b0, uint32_t b1)
{
    asm volatile("mma.sync.aligned.m16n8k16.row.col.f32.f16.f16.f32 "
                 "{%0,%1,%2,%3}, {%4,%5,%6,%7}, {%8,%9}, {%0,%1,%2,%3};"
                 : "+f"(d0), "+f"(d1), "+f"(d2), "+f"(d3)
                 : "r"(a0), "r"(a1), "r"(a2), "r"(a3), "r"(b0), "r"(b1));
}
__device__ __forceinline__ uint32_t pack_h2(float lo, float hi)
{
    __half2 h = __floats2half2_rn(lo, hi);
    return *reinterpret_cast<uint32_t*>(&h);
}

// ---------------------------------------------------------------------------
// x transform: x[b, i, t, f] -> g_xh[(b*32+ip)][f][t] = half2{x[2ip], x[2ip+1]}
// ---------------------------------------------------------------------------
__global__ void xtrans(const float* __restrict__ x)
{
    __shared__ uint32_t tile[32][33];
    const int plane = blockIdx.z;            // b*32 + ip
    const int b  = plane >> 5;
    const int ip = plane & 31;
    const int f0 = blockIdx.x * 32, tg0 = blockIdx.y * 32;
    const float* s0 = x + (size_t)(b * CIN + 2 * ip    ) * TDIM * FDIM;
    const float* s1 = x + (size_t)(b * CIN + 2 * ip + 1) * TDIM * FDIM;
#pragma unroll
    for (int r = threadIdx.y; r < 32; r += 8) {
        int f = f0 + threadIdx.x;
        float v0 = 0.f, v1 = 0.f;
        if (f < FDIM) {
            size_t off = (size_t)(tg0 + r) * FDIM + f;
            v0 = s0[off]; v1 = s1[off];
        }
        tile[r][threadIdx.x] = pack_h2(v0, v1);
    }
    __syncthreads();
    uint32_t* dst = g_xh + (size_t)plane * FDIM * TDIM;
#pragma unroll
    for (int r = threadIdx.y; r < 32; r += 8) {
        int f = f0 + r;
        if (f < FDIM) dst[(size_t)f * TDIM + tg0 + threadIdx.x] = tile[threadIdx.x][r];
    }
}

// ---------------------------------------------------------------------------
// out transpose: g_oh[(b*64+o)][f][t/2] (half2) -> out[b,o,t,f] (f32)
// ---------------------------------------------------------------------------
__global__ void __launch_bounds__(256)
otrans(float* __restrict__ out)
{
    __shared__ float tile[32][129];
    const int plane = blockIdx.z;            // b*COUT + o
    const int tg0 = blockIdx.x * 128;
    const int f0  = blockIdx.y * 32;
    const int tx  = threadIdx.x & 31;
    const int ty  = threadIdx.x >> 5;        // 0..7
    const uint32_t* src = g_oh + (size_t)plane * FDIM * (TDIM / 2);

#pragma unroll
    for (int k = 0; k < 4; k++) {
        int fl = ty + 8 * k;
        int f  = f0 + fl;
        if (f < FDIM) {
            uint2 v = *reinterpret_cast<const uint2*>(src + (size_t)f * (TDIM / 2)
                                                      + (tg0 >> 1) + tx * 2);
            __half2 h0 = *reinterpret_cast<__half2*>(&v.x);
            __half2 h1 = *reinterpret_cast<__half2*>(&v.y);
            tile[fl][tx * 4 + 0] = __low2float(h0);
            tile[fl][tx * 4 + 1] = __high2float(h0);
            tile[fl][tx * 4 + 2] = __low2float(h1);
            tile[fl][tx * 4 + 3] = __high2float(h1);
        }
    }
    __syncthreads();

    const int f = f0 + tx;
    if (f < FDIM) {
        float* dst = out + (size_t)plane * TDIM * FDIM + (size_t)tg0 * FDIM + f;
#pragma unroll
        for (int k = 0; k < 16; k++) {
            int tl = ty * 16 + k;
            dst[(size_t)tl * FDIM] = tile[tx][tl];
        }
    }
}

// ---------------------------------------------------------------------------
// Weight transform -> m16n8k16 fragment-ordered half2 A tiles, M=64, K=144/chunk.
// ---------------------------------------------------------------------------
__global__ void wtrans(const float* __restrict__ w)
{
    long idx = (long)blockIdx.x * 256 + threadIdx.x;
    const long total = (long)FDIM * NCHK * ATILE_W;
    if (idx >= total) return;
    int e    = (int)(idx % ATILE_W);
    int tile = (int)(idx / ATILE_W);
    int ch = tile & 3;
    int f  = tile >> 2;
    int r  = e & 3;
    int l  = (e >> 2) & 31;
    int mt = (e >> 7) & 3;
    int s  = e >> 9;
    int o  = mt * 16 + (l >> 2) + 8 * (r & 1);
    int ip = (l & 3) + 4 * (r >> 1);
    int i0 = ch * 16 + 2 * ip;
    int m  = s / 3, n = s % 3;
    float v0 = w[(((size_t)(o * CIN + i0    ) * FDIM + f) * 3 + m) * 3 + n];
    float v1 = w[(((size_t)(o * CIN + i0 + 1) * FDIM + f) * 3 + m) * 3 + n];
    g_wA[idx] = pack_h2(v0, v1);
}

// ---------------------------------------------------------------------------
// Main kernel: CTA = (f, t-tile, b) -> g_oh[b*64+o][f][t0/2 : (t0+256)/2]
// 8 warps: warp_m = wid&1 (32 rows), warp_n = wid>>1 (64 cols, nt=8)
// occupancy 2 (regs capped at 128; 2x87.5KB smem fits)
// ---------------------------------------------------------------------------
__global__ void __launch_bounds__(NTHR, 2)
conv_mma(const float* __restrict__ bias)
{
    extern __shared__ __align__(16) char smem[];
    const uint32_t sbase = smem_u32(smem);
    const int tid    = threadIdx.x;
    const int wid    = tid >> 5;
    const int lane   = tid & 31;
    const int warp_m = wid & 1;
    const int warp_n = wid >> 1;            // 0..3, 64 cols each
    const int f      = blockIdx.x;
    const int t0     = blockIdx.y * TT;
    const int b      = blockIdx.z;

    // ---- accumulators init with bias ----
    float D[2][8][4];
#pragma unroll
    for (int w2 = 0; w2 < 2; w2++) {
#pragma unroll
        for (int h = 0; h < 2; h++) {
            int o = warp_m * 32 + w2 * 16 + (lane >> 2) + 8 * h;
            float bv = bias[o * FDIM + f];
#pragma unroll
            for (int nt = 0; nt < 8; nt++) {
                D[w2][nt][2 * h + 0] = bv;
                D[w2][nt][2 * h + 1] = bv;
            }
        }
    }

    // ---- chunk prefetch: A (pre-packed) + xh rows, all 16B cp.async ----
    auto prefetch = [&](int c, int buf) {
        const float4* asrc = (const float4*)(g_wA + (size_t)(f * NCHK + c) * ATILE_W);
        uint32_t ad = sbase + (buf ? SM_A1 : SM_A0);
        for (int q = tid; q < ATILE_W / 4; q += NTHR)      // 1152 float4
            cp_async16(ad + q * 16, asrc + q);
        uint32_t xd = sbase + (buf ? SM_X1 : SM_X0);
        for (int e = tid; e < XROWS * 66; e += NTHR) {     // 1584 float4
            int r  = e / 66;
            int j4 = e - r * 66;
            int il = r / 3;
            int n  = r - il * 3;
            int fq = f - 1 + n;
            int ts = t0 - 4 + j4 * 4;
            bool ok = (fq >= 0) & (fq < FDIM) & (ts >= 0) & (ts < TDIM);
            const uint32_t* src = g_xh + ((size_t)(b * 32 + c * 8 + il) * FDIM + (ok ? fq : 0)) * TDIM
                                       + (ok ? ts : 0);
            cp_async16z(xd + (uint32_t)(r * SXR + j4 * 4) * 4u, src, ok);
        }
        asm volatile("cp.async.commit_group;\n");
    };

    prefetch(0, 0);

    for (int c = 0; c < NCHK; c++) {
        if (c + 1 < NCHK) {
            prefetch(c + 1, (c + 1) & 1);
            asm volatile("cp.async.wait_group 1;\n");
        } else {
            asm volatile("cp.async.wait_group 0;\n");
        }
        __syncthreads();
        // NOTE: no end-of-loop barrier needed — a warp cannot reach the
        // prefetch that overwrites buffer X until all warps passed this
        // barrier for the iteration that finished reading X.

        const int buf = c & 1;
        const uint32_t* asb = (const uint32_t*)(smem + (buf ? SM_A1 : SM_A0));
        const uint32_t* xsb = (const uint32_t*)(smem + (buf ? SM_X1 : SM_X0));

        const int r3 = lane & 3;
        const int tB = warp_n * 64 + (lane >> 2);
#pragma unroll
        for (int s = 0; s < NSTEP; s++) {
            const int m_s = s / 3, n_s = s % 3;
            uint32_t a[2][4];
#pragma unroll
            for (int w2 = 0; w2 < 2; w2++) {
                const uint4* ap = (const uint4*)asb +
                                  ((s * 4 + warp_m * 2 + w2) * 32 + lane);
                uint4 av = *ap;
                a[w2][0] = av.x; a[w2][1] = av.y; a[w2][2] = av.z; a[w2][3] = av.w;
            }
            // B word addr: (ip_loc*3 + n_s)*SXR + 3 + m_s + t ; b1 at ip_loc+4
            const uint32_t* brow = xsb + (r3 * 3 + n_s) * SXR + 3 + m_s + tB;
#pragma unroll
            for (int nt = 0; nt < 8; nt++) {
                uint32_t b0 = brow[nt * 8];
                uint32_t b1 = brow[nt * 8 + 12 * SXR];
                mma_f16(D[0][nt][0], D[0][nt][1], D[0][nt][2], D[0][nt][3],
                        a[0][0], a[0][1], a[0][2], a[0][3], b0, b1);
                mma_f16(D[1][nt][0], D[1][nt][1], D[1][nt][2], D[1][nt][3],
                        a[1][0], a[1][1], a[1][2], a[1][3], b0, b1);
            }
        }
        if (c + 1 < NCHK) __syncthreads();   // only separates read-phase from next wait; cheap
    }

    // ---- epilogue: half2-packed coalesced stores along t into g_oh ----
#pragma unroll
    for (int w2 = 0; w2 < 2; w2++) {
#pragma unroll
        for (int h = 0; h < 2; h++) {
            int o = warp_m * 32 + w2 * 16 + (lane >> 2) + 8 * h;
            uint32_t* op = g_oh + ((size_t)(b * COUT + o) * FDIM + f) * (TDIM / 2)
                         + ((t0 + warp_n * 64) >> 1);
#pragma unroll
            for (int nt = 0; nt < 8; nt++) {
                int tw = nt * 4 + (lane & 3);   // word index (pair of t)
                op[tw] = pack_h2(D[w2][nt][2 * h + 0], D[w2][nt][2 * h + 1]);
            }
        }
    }
}

// ---------------------------------------------------------------------------
extern "C" void kernel_launch(void* const* d_in, const int* in_sizes, int n_in,
                              void* d_out, int out_size)
{
    const float* x    = (const float*)d_in[0];
    const float* w    = (const float*)d_in[1];
    const float* bias = (const float*)d_in[2];
    float* out        = (float*)d_out;

    cudaFuncSetAttribute(conv_mma, cudaFuncAttributeMaxDynamicSharedMemorySize, SM_TOTAL);

    dim3 tb(32, 8);
    xtrans<<<dim3((FDIM + 31) / 32, TDIM / 32, CB * 32), tb>>>(x);

    const long total = (long)FDIM * NCHK * ATILE_W;
    wtrans<<<(unsigned)((total + 255) / 256), 256>>>(w);

    dim3 grid(FDIM, NT, CB);
    conv_mma<<<grid, NTHR, SM_TOTAL>>>(bias);

    otrans<<<dim3(TDIM / 128, (FDIM + 31) / 32, CB * COUT), 256>>>(out);
}

// round 15
// speedup vs baseline: 2.7036x; 1.1513x over previous
#include <cuda_runtime.h>
#include <cuda_fp16.h>
#include <cstdint>
#include <cstddef>

#define CB    8
#define CIN   64
#define COUT  64
#define TDIM  512
#define FDIM  161

constexpr int NCHK  = 4;           // chunks of 16 channels (8 half2 pairs)
constexpr int TT    = 256;         // t-tile (GEMM N)
constexpr int NT    = TDIM / TT;   // 2
constexpr int NSTEP = 9;           // k16 steps per chunk (K_chunk = 144 = 16i * 9(m,n))
constexpr int NTHR  = 256;         // 8 warps

// A tile per (f,chunk): fragment-ordered half2 words [step][mtile(4)][lane][4]
constexpr int ATILE_W = NSTEP * 4 * 32 * 4;   // 4608 words = 18432 B
// X tile: 24 rows [ip_loc*3+n], each row = 264 half2 words over t (t0-4 .. t0+259)
constexpr int SXR   = 264;                    // word stride; 264 % 32 == 8 (bank spread)
constexpr int XROWS = 24;
constexpr int XWRD  = XROWS * SXR;            // 6336 words = 25344 B

constexpr int SM_A0 = 0;
constexpr int SM_A1 = 18432;
constexpr int SM_X0 = 36864;
constexpr int SM_X1 = SM_X0 + XWRD * 4;       // 62208
constexpr int SM_TOTAL = SM_X1 + XWRD * 4;    // 87552 B (x2 CTAs = 175KB <= 227KB)

// Output stage: 64 rows x 132 words = 33792 B. Spans X0+X1 region (50688 B) —
// ONLY valid after a barrier that retires all mainloop smem reads.
constexpr int SOW = 132;                      // stride: 132%32==4 -> conflict-free

// Merged prep kernel grid split
constexpr int XT_BLKS = 6 * (TDIM / 32) * (CB * 32);            // 6*16*256 = 24576
constexpr long WT_TOTAL = (long)FDIM * NCHK * ATILE_W;          // 2.97M elements
constexpr int WT_BLKS = (int)((WT_TOTAL + 255) / 256);          // 11592

__device__ uint32_t g_wA[(size_t)FDIM * NCHK * ATILE_W];        // 11.9 MB (half2 words)
__device__ uint32_t g_xh[(size_t)CB * 32 * FDIM * TDIM];        // x: [b*ip][f][t] half2 pairs
__device__ uint32_t g_oh[(size_t)CB * COUT * FDIM * (TDIM/2)];  // out staging: [b*o][f][t/2]

// ---------------------------------------------------------------------------
__device__ __forceinline__ void cp_async16(uint32_t s, const void* g)
{
    asm volatile("cp.async.ca.shared.global [%0], [%1], 16;\n" :: "r"(s), "l"(g));
}
__device__ __forceinline__ void cp_async16z(uint32_t s, const void* g, bool ok)
{
    int sz = ok ? 16 : 0;
    asm volatile("cp.async.ca.shared.global [%0], [%1], 16, %2;\n" :: "r"(s), "l"(g), "r"(sz));
}
__device__ __forceinline__ uint32_t smem_u32(const void* p)
{
    uint32_t a;
    asm("{ .reg .u64 t; cvta.to.shared.u64 t, %1; cvt.u32.u64 %0, t; }" : "=r"(a) : "l"(p));
    return a;
}
__device__ __forceinline__ void mma_f16(float& d0, float& d1, float& d2, float& d3,
                                        uint32_t a0, uint32_t a1, uint32_t a2, uint32_t a3,
                                        uint32_t b0, uint32_t b1)
{
    asm volatile("mma.sync.aligned.m16n8k16.row.col.f32.f16.f16.f32 "
                 "{%0,%1,%2,%3}, {%4,%5,%6,%7}, {%8,%9}, {%0,%1,%2,%3};"
                 : "+f"(d0), "+f"(d1), "+f"(d2), "+f"(d3)
                 : "r"(a0), "r"(a1), "r"(a2), "r"(a3), "r"(b0), "r"(b1));
}
__device__ __forceinline__ uint32_t pack_h2(float lo, float hi)
{
    __half2 h = __floats2half2_rn(lo, hi);
    return *reinterpret_cast<uint32_t*>(&h);
}

// ---------------------------------------------------------------------------
// Merged prep: xtrans blocks [0, XT_BLKS) + wtrans blocks [XT_BLKS, ...)
// ---------------------------------------------------------------------------
__global__ void __launch_bounds__(256)
prep(const float* __restrict__ x, const float* __restrict__ w)
{
    __shared__ uint32_t tile[32][33];
    const int bid = blockIdx.x;

    if (bid < XT_BLKS) {
        // ---- xtrans: x[b,i,t,f] -> g_xh[(b*32+ip)][f][t] = half2{x[2ip],x[2ip+1]} ----
        const int plane = bid / 96;              // b*32 + ip
        const int rem   = bid - plane * 96;
        const int fblk  = rem % 6;
        const int tblk  = rem / 6;
        const int b  = plane >> 5;
        const int ip = plane & 31;
        const int f0 = fblk * 32, tg0 = tblk * 32;
        const int tx = threadIdx.x & 31;
        const int ty = threadIdx.x >> 5;         // 0..7
        const float* s0 = x + (size_t)(b * CIN + 2 * ip    ) * TDIM * FDIM;
        const float* s1 = x + (size_t)(b * CIN + 2 * ip + 1) * TDIM * FDIM;
#pragma unroll
        for (int r = ty; r < 32; r += 8) {
            int f = f0 + tx;
            float v0 = 0.f, v1 = 0.f;
            if (f < FDIM) {
                size_t off = (size_t)(tg0 + r) * FDIM + f;
                v0 = s0[off]; v1 = s1[off];
            }
            tile[r][tx] = pack_h2(v0, v1);
        }
        __syncthreads();
        uint32_t* dst = g_xh + (size_t)plane * FDIM * TDIM;
#pragma unroll
        for (int r = ty; r < 32; r += 8) {
            int f = f0 + r;
            if (f < FDIM) dst[(size_t)f * TDIM + tg0 + tx] = tile[tx][r];
        }
    } else {
        // ---- wtrans: kernel[o][i][f][m][n] -> fragment-ordered half2 A tiles ----
        long idx = (long)(bid - XT_BLKS) * 256 + threadIdx.x;
        if (idx >= WT_TOTAL) return;
        int e    = (int)(idx % ATILE_W);
        int tl   = (int)(idx / ATILE_W);
        int ch = tl & 3;
        int f  = tl >> 2;
        int r  = e & 3;
        int l  = (e >> 2) & 31;
        int mt = (e >> 7) & 3;
        int s  = e >> 9;
        int o  = mt * 16 + (l >> 2) + 8 * (r & 1);
        int ip = (l & 3) + 4 * (r >> 1);
        int i0 = ch * 16 + 2 * ip;
        int m  = s / 3, n = s % 3;
        float v0 = w[(((size_t)(o * CIN + i0    ) * FDIM + f) * 3 + m) * 3 + n];
        float v1 = w[(((size_t)(o * CIN + i0 + 1) * FDIM + f) * 3 + m) * 3 + n];
        g_wA[idx] = pack_h2(v0, v1);
    }
}

// ---------------------------------------------------------------------------
// out transpose: g_oh[(b*64+o)][f][t/2] (half2) -> out[b,o,t,f] (f32)
// ---------------------------------------------------------------------------
__global__ void __launch_bounds__(256)
otrans(float* __restrict__ out)
{
    __shared__ float tile[32][129];
    const int plane = blockIdx.z;            // b*COUT + o
    const int tg0 = blockIdx.x * 128;
    const int f0  = blockIdx.y * 32;
    const int tx  = threadIdx.x & 31;
    const int ty  = threadIdx.x >> 5;        // 0..7
    const uint32_t* src = g_oh + (size_t)plane * FDIM * (TDIM / 2);

#pragma unroll
    for (int k = 0; k < 4; k++) {
        int fl = ty + 8 * k;
        int f  = f0 + fl;
        if (f < FDIM) {
            uint2 v = *reinterpret_cast<const uint2*>(src + (size_t)f * (TDIM / 2)
                                                      + (tg0 >> 1) + tx * 2);
            __half2 h0 = *reinterpret_cast<__half2*>(&v.x);
            __half2 h1 = *reinterpret_cast<__half2*>(&v.y);
            tile[fl][tx * 4 + 0] = __low2float(h0);
            tile[fl][tx * 4 + 1] = __high2float(h0);
            tile[fl][tx * 4 + 2] = __low2float(h1);
            tile[fl][tx * 4 + 3] = __high2float(h1);
        }
    }
    __syncthreads();

    const int f = f0 + tx;
    if (f < FDIM) {
        float* dst = out + (size_t)plane * TDIM * FDIM + (size_t)tg0 * FDIM + f;
#pragma unroll
        for (int k = 0; k < 16; k++) {
            int tl = ty * 16 + k;
            dst[(size_t)tl * FDIM] = tile[tx][tl];
        }
    }
}

// ---------------------------------------------------------------------------
// Main kernel: CTA = (f, t-tile, b) -> g_oh[b*64+o][f][t0/2 : (t0+256)/2]
// 8 warps: warp_m = wid&1 (32 rows), warp_n = wid>>1 (64 cols, nt=8); occ 2
// ---------------------------------------------------------------------------
__global__ void __launch_bounds__(NTHR, 2)
conv_mma(const float* __restrict__ bias)
{
    extern __shared__ __align__(16) char smem[];
    const uint32_t sbase = smem_u32(smem);
    const int tid    = threadIdx.x;
    const int wid    = tid >> 5;
    const int lane   = tid & 31;
    const int warp_m = wid & 1;
    const int warp_n = wid >> 1;            // 0..3, 64 cols each
    const int f      = blockIdx.x;
    const int t0     = blockIdx.y * TT;
    const int b      = blockIdx.z;

    // ---- accumulators init with bias ----
    float D[2][8][4];
#pragma unroll
    for (int w2 = 0; w2 < 2; w2++) {
#pragma unroll
        for (int h = 0; h < 2; h++) {
            int o = warp_m * 32 + w2 * 16 + (lane >> 2) + 8 * h;
            float bv = bias[o * FDIM + f];
#pragma unroll
            for (int nt = 0; nt < 8; nt++) {
                D[w2][nt][2 * h + 0] = bv;
                D[w2][nt][2 * h + 1] = bv;
            }
        }
    }

    // ---- chunk prefetch: A (pre-packed) + xh rows, all 16B cp.async ----
    auto prefetch = [&](int c, int buf) {
        const float4* asrc = (const float4*)(g_wA + (size_t)(f * NCHK + c) * ATILE_W);
        uint32_t ad = sbase + (buf ? SM_A1 : SM_A0);
        for (int q = tid; q < ATILE_W / 4; q += NTHR)      // 1152 float4
            cp_async16(ad + q * 16, asrc + q);
        uint32_t xd = sbase + (buf ? SM_X1 : SM_X0);
        for (int e = tid; e < XROWS * 66; e += NTHR) {     // 1584 float4
            int r  = e / 66;
            int j4 = e - r * 66;
            int il = r / 3;
            int n  = r - il * 3;
            int fq = f - 1 + n;
            int ts = t0 - 4 + j4 * 4;
            bool ok = (fq >= 0) & (fq < FDIM) & (ts >= 0) & (ts < TDIM);
            const uint32_t* src = g_xh + ((size_t)(b * 32 + c * 8 + il) * FDIM + (ok ? fq : 0)) * TDIM
                                       + (ok ? ts : 0);
            cp_async16z(xd + (uint32_t)(r * SXR + j4 * 4) * 4u, src, ok);
        }
        asm volatile("cp.async.commit_group;\n");
    };

    prefetch(0, 0);

    for (int c = 0; c < NCHK; c++) {
        if (c + 1 < NCHK) {
            prefetch(c + 1, (c + 1) & 1);
            asm volatile("cp.async.wait_group 1;\n");
        } else {
            asm volatile("cp.async.wait_group 0;\n");
        }
        __syncthreads();

        const int buf = c & 1;
        const uint32_t* asb = (const uint32_t*)(smem + (buf ? SM_A1 : SM_A0));
        const uint32_t* xsb = (const uint32_t*)(smem + (buf ? SM_X1 : SM_X0));

        const int r3 = lane & 3;
        const int tB = warp_n * 64 + (lane >> 2);
#pragma unroll
        for (int s = 0; s < NSTEP; s++) {
            const int m_s = s / 3, n_s = s % 3;
            uint32_t a[2][4];
#pragma unroll
            for (int w2 = 0; w2 < 2; w2++) {
                const uint4* ap = (const uint4*)asb +
                                  ((s * 4 + warp_m * 2 + w2) * 32 + lane);
                uint4 av = *ap;
                a[w2][0] = av.x; a[w2][1] = av.y; a[w2][2] = av.z; a[w2][3] = av.w;
            }
            // B word addr: (ip_loc*3 + n_s)*SXR + 3 + m_s + t ; b1 at ip_loc+4
            const uint32_t* brow = xsb + (r3 * 3 + n_s) * SXR + 3 + m_s + tB;
#pragma unroll
            for (int nt = 0; nt < 8; nt++) {
                uint32_t b0 = brow[nt * 8];
                uint32_t b1 = brow[nt * 8 + 12 * SXR];
                mma_f16(D[0][nt][0], D[0][nt][1], D[0][nt][2], D[0][nt][3],
                        a[0][0], a[0][1], a[0][2], a[0][3], b0, b1);
                mma_f16(D[1][nt][0], D[1][nt][1], D[1][nt][2], D[1][nt][3],
                        a[1][0], a[1][1], a[1][2], a[1][3], b0, b1);
            }
        }
        if (c + 1 < NCHK) __syncthreads();
    }

    // ---- epilogue: stage in smem, then coalesced STG ----
    // BARRIER REQUIRED: stage (33.8KB) spans X0+X1; every warp must be done
    // reading X1 (last chunk's B data) before any warp writes the stage.
    __syncthreads();
    uint32_t* stage = (uint32_t*)(smem + SM_X0);   // 64 x SOW words across X0+X1
#pragma unroll
    for (int w2 = 0; w2 < 2; w2++) {
#pragma unroll
        for (int h = 0; h < 2; h++) {
            int o = warp_m * 32 + w2 * 16 + (lane >> 2) + 8 * h;
            uint32_t* sp = stage + o * SOW + warp_n * 32;
#pragma unroll
            for (int nt = 0; nt < 8; nt++) {
                int tw = nt * 4 + (lane & 3);
                sp[tw] = pack_h2(D[w2][nt][2 * h + 0], D[w2][nt][2 * h + 1]);
            }
        }
    }
    __syncthreads();
    // copy: warp w writes rows o = w, w+8, ..., 512B contiguous per row
#pragma unroll
    for (int it = 0; it < 8; it++) {
        int o = wid + 8 * it;
        uint4 v = *reinterpret_cast<const uint4*>(stage + o * SOW + lane * 4);
        uint32_t* gp = g_oh + ((size_t)(b * COUT + o) * FDIM + f) * (TDIM / 2)
                     + (t0 >> 1) + lane * 4;
        *reinterpret_cast<uint4*>(gp) = v;
    }
}

// ---------------------------------------------------------------------------
extern "C" void kernel_launch(void* const* d_in, const int* in_sizes, int n_in,
                              void* d_out, int out_size)
{
    const float* x    = (const float*)d_in[0];
    const float* w    = (const float*)d_in[1];
    const float* bias = (const float*)d_in[2];
    float* out        = (float*)d_out;

    cudaFuncSetAttribute(conv_mma, cudaFuncAttributeMaxDynamicSharedMemorySize, SM_TOTAL);

    prep<<<XT_BLKS + WT_BLKS, 256>>>(x, w);

    dim3 grid(FDIM, NT, CB);
    conv_mma<<<grid, NTHR, SM_TOTAL>>>(bias);

    otrans<<<dim3(TDIM / 128, (FDIM + 31) / 32, CB * COUT), 256>>>(out);
}